// round 4
// baseline (speedup 1.0000x reference)
#include <cuda_runtime.h>

// Problem constants (fixed shapes from reference setup_inputs)
#define BB 16
#define SS 64
#define II 128
#define HH 512
#define TT 5
#define H4 (HH / 4)   // 128 float4 lanes across H

// Scratch: cur[b,s,h] = sum_i x[b,s,i,h] * enc[i,h]   (2 MB)
__device__ float g_cur[BB * SS * HH];

// ---------------------------------------------------------------------------
// Kernel 1: weighted reduction over I.
// Grid: (H4/32, BS/8) = (4, 128), block = 256 threads (8 bs-rows x 32 h4-lanes).
// Each block touches a 128(i) x 128(h-floats) encoding slice (64 KB); all 8
// bs-rows read the same encoding addresses in lockstep -> L1 broadcast hits,
// so encoding contributes ~32 MB of L2 traffic instead of 268 MB.
// x reads are fully coalesced float4 (adjacent lanes = adjacent h4).
// ---------------------------------------------------------------------------
__global__ __launch_bounds__(256)
void reduce_kernel(const float* __restrict__ x,
                   const float* __restrict__ enc,
                   float* __restrict__ cur) {
    const int tx = threadIdx.x & 31;          // h4 lane within chunk
    const int r  = threadIdx.x >> 5;          // bs row within block
    const int h4 = blockIdx.x * 32 + tx;      // 0..127
    const int bs = blockIdx.y * 8 + r;        // 0..1023

    const float4* __restrict__ x4 = reinterpret_cast<const float4*>(x);
    const float4* __restrict__ e4 = reinterpret_cast<const float4*>(enc);

    const float4* xp = x4 + (long)bs * II * H4 + h4;
    const float4* ep = e4 + h4;

    float4 acc = make_float4(0.f, 0.f, 0.f, 0.f);

    #pragma unroll 8
    for (int i = 0; i < II; i++) {
        float4 xv = xp[i * H4];
        float4 ev = ep[i * H4];
        acc.x = fmaf(xv.x, ev.x, acc.x);
        acc.y = fmaf(xv.y, ev.y, acc.y);
        acc.z = fmaf(xv.z, ev.z, acc.z);
        acc.w = fmaf(xv.w, ev.w, acc.w);
    }

    reinterpret_cast<float4*>(cur)[(long)bs * H4 + h4] = acc;
}

// ---------------------------------------------------------------------------
// Kernel 2: LIF dynamics. One thread per (b,h) chain, 8192 chains, each runs
// the full S*T = 320-step recurrence. v carries across the entire sequence
// (matches lax.scan with a single v0). Coalesced: lanes cover contiguous h.
// ---------------------------------------------------------------------------
__global__ __launch_bounds__(64)
void snn_kernel(const float* __restrict__ cur, float* __restrict__ out) {
    const int tid = blockIdx.x * blockDim.x + threadIdx.x;   // 0..8191
    const int b = tid >> 9;          // /512
    const int h = tid & (HH - 1);

    const float* cp = cur + (long)b * SS * HH + h;
    float* op = out + (long)b * SS * TT * HH + h;

    float v = 0.0f;
    for (int s = 0; s < SS; s++) {
        const float c = cp[s * HH];
        float* o = op + s * TT * HH;
        #pragma unroll
        for (int t = 0; t < TT; t++) {
            v = fmaf(0.9f, v, c);            // v = ALPHA*v + i_t
            float z = (v > 1.0f) ? 1.0f : 0.0f;  // spike(v - THRESHOLD)
            v -= z;                          // soft reset (THRESHOLD = 1)
            o[t * HH] = z;
        }
    }
}

extern "C" void kernel_launch(void* const* d_in, const int* in_sizes, int n_in,
                              void* d_out, int out_size) {
    const float* x   = (const float*)d_in[0];   // [B,S,I,H] f32
    const float* enc = (const float*)d_in[1];   // [I,H] f32
    float* out = (float*)d_out;                 // [B, S*T, H] f32

    float* cur;
    cudaGetSymbolAddress((void**)&cur, g_cur);

    dim3 g1(H4 / 32, (BB * SS) / 8);            // (4, 128)
    reduce_kernel<<<g1, 256>>>(x, enc, cur);

    snn_kernel<<<(BB * HH) / 64, 64>>>(cur, out);
}

// round 9
// speedup vs baseline: 1.0578x; 1.0578x over previous
#include <cuda_runtime.h>

// Problem constants (fixed shapes from reference setup_inputs)
#define BB 16
#define SS 64
#define II 128
#define HH 512
#define TT 5
#define H4 (HH / 4)   // 128 float4 lanes across H
#define CH 16         // s-steps per chunk (SS/CH = 4 chunks)

// Scratch: cur[b,s,h] = sum_i x[b,s,i,h] * enc[i,h]   (2 MB)
__device__ float g_cur[BB * SS * HH];

// ---------------------------------------------------------------------------
// Kernel 1: weighted reduction over I.  (measured ~46us, ~5.8 TB/s — near HBM
// roofline for the compulsory 268 MB of x; unchanged)
// Grid: (4, 128), block = 256 (8 bs-rows x 32 h4-lanes). All 8 bs-rows read
// the same 64KB encoding slice in lockstep -> L1 broadcast hits.
// ---------------------------------------------------------------------------
__global__ __launch_bounds__(256)
void reduce_kernel(const float* __restrict__ x,
                   const float* __restrict__ enc,
                   float* __restrict__ cur) {
    const int tx = threadIdx.x & 31;
    const int r  = threadIdx.x >> 5;
    const int h4 = blockIdx.x * 32 + tx;
    const int bs = blockIdx.y * 8 + r;

    const float4* __restrict__ x4 = reinterpret_cast<const float4*>(x);
    const float4* __restrict__ e4 = reinterpret_cast<const float4*>(enc);

    const float4* xp = x4 + (long)bs * II * H4 + h4;
    const float4* ep = e4 + h4;

    float4 acc = make_float4(0.f, 0.f, 0.f, 0.f);

    #pragma unroll 8
    for (int i = 0; i < II; i++) {
        float4 xv = xp[i * H4];
        float4 ev = ep[i * H4];
        acc.x = fmaf(xv.x, ev.x, acc.x);
        acc.y = fmaf(xv.y, ev.y, acc.y);
        acc.z = fmaf(xv.z, ev.z, acc.z);
        acc.w = fmaf(xv.w, ev.w, acc.w);
    }

    reinterpret_cast<float4*>(cur)[(long)bs * H4 + h4] = acc;
}

// ---------------------------------------------------------------------------
// Kernel 2: LIF dynamics. One thread per (b,h) chain, 8192 chains.
// Software-pipelined chunks: preload 16 cur values (registers), and while
// running the 80-step recurrence on the current chunk the next chunk's 16
// independent loads are already in flight — their ~300cyc L2 drain hides
// under ~1000cyc of compute. Per-step critical path ~12 cyc:
//   FFMA(v) -> {FSETP p || FADD vm1} -> FSEL v;  z-select + STG off-path.
// Outer chunk loop rolled -> ~10KB body, bounded compile time & I$ footprint.
// ---------------------------------------------------------------------------
__global__ __launch_bounds__(64)
void snn_kernel(const float* __restrict__ cur, float* __restrict__ out) {
    const int tid = blockIdx.x * blockDim.x + threadIdx.x;   // 0..8191
    const int b = tid >> 9;          // /512
    const int h = tid & (HH - 1);

    const float* cp = cur + (long)b * SS * HH + h;
    float* op = out + (long)b * SS * TT * HH + h;

    float c[CH], cn[CH];

    // Prologue: load chunk 0.
    #pragma unroll
    for (int j = 0; j < CH; j++) c[j] = __ldg(cp + j * HH);

    float v = 0.0f;
    for (int k = 0; k < SS / CH; k++) {
        // Issue next chunk's loads before touching this chunk's values.
        const int nbase = (k + 1) * CH;
        if (k + 1 < SS / CH) {
            #pragma unroll
            for (int j = 0; j < CH; j++) cn[j] = __ldg(cp + (nbase + j) * HH);
        }

        float* ok = op + k * CH * TT * HH;
        #pragma unroll
        for (int s = 0; s < CH; s++) {
            const float cs = c[s];
            float* o = ok + s * TT * HH;
            #pragma unroll
            for (int t = 0; t < TT; t++) {
                v = fmaf(0.9f, v, cs);           // v = ALPHA*v + i_t   (4 cyc)
                const bool  p   = (v > 1.0f);    // FSETP, off FFMA     (4 cyc)
                const float vm1 = v - 1.0f;      // FADD, || with FSETP
                o[t * HH] = p ? 1.0f : 0.0f;     // z, off critical path
                v = p ? vm1 : v;                 // FSEL                (4 cyc)
            }
        }

        #pragma unroll
        for (int j = 0; j < CH; j++) c[j] = cn[j];
    }
}

extern "C" void kernel_launch(void* const* d_in, const int* in_sizes, int n_in,
                              void* d_out, int out_size) {
    const float* x   = (const float*)d_in[0];   // [B,S,I,H] f32
    const float* enc = (const float*)d_in[1];   // [I,H] f32
    float* out = (float*)d_out;                 // [B, S*T, H] f32

    float* cur;
    cudaGetSymbolAddress((void**)&cur, g_cur);

    dim3 g1(H4 / 32, (BB * SS) / 8);            // (4, 128)
    reduce_kernel<<<g1, 256>>>(x, enc, cur);

    snn_kernel<<<(BB * HH) / 64, 64>>>(cur, out);
}

// round 12
// speedup vs baseline: 1.0708x; 1.0123x over previous
#include <cuda_runtime.h>

// Problem constants (fixed shapes from reference setup_inputs)
#define BB 16
#define SS 64
#define II 128
#define HH 512
#define TT 5
#define H4 (HH / 4)   // 128 float4 lanes across H
#define CH 16         // s-steps per chunk (SS/CH = 4 chunks)

// Scratch: cur[b,s,h] = sum_i x[b,s,i,h] * enc[i,h]   (2 MB)
__device__ float g_cur[BB * SS * HH];

// ---------------------------------------------------------------------------
// Kernel 1: weighted reduction over I.  ~49us, ~5.5 TB/s (near this pattern's
// DRAM ceiling). R10: x loads use .cs (streaming, evict-first) so the 64KB
// encoding slice stays resident in L1; cur stores use .cs too.
// Grid: (4, 128), block = 256 (8 bs-rows x 32 h4-lanes).
// ---------------------------------------------------------------------------
__global__ __launch_bounds__(256)
void reduce_kernel(const float* __restrict__ x,
                   const float* __restrict__ enc,
                   float* __restrict__ cur) {
    const int tx = threadIdx.x & 31;
    const int r  = threadIdx.x >> 5;
    const int h4 = blockIdx.x * 32 + tx;
    const int bs = blockIdx.y * 8 + r;

    const float4* __restrict__ x4 = reinterpret_cast<const float4*>(x);
    const float4* __restrict__ e4 = reinterpret_cast<const float4*>(enc);

    const float4* xp = x4 + (long)bs * II * H4 + h4;
    const float4* ep = e4 + h4;

    float4 acc = make_float4(0.f, 0.f, 0.f, 0.f);

    #pragma unroll 8
    for (int i = 0; i < II; i++) {
        float4 xv = __ldcs(xp + i * H4);   // streaming: don't pollute L1
        float4 ev = __ldg(ep + i * H4);    // resident: L1 broadcast across rows
        acc.x = fmaf(xv.x, ev.x, acc.x);
        acc.y = fmaf(xv.y, ev.y, acc.y);
        acc.z = fmaf(xv.z, ev.z, acc.z);
        acc.w = fmaf(xv.w, ev.w, acc.w);
    }

    __stcs(reinterpret_cast<float4*>(cur) + (long)bs * H4 + h4, acc);
}

// ---------------------------------------------------------------------------
// Kernel 2: LIF dynamics. One thread per (b,h) chain, 8192 chains.
// Chunked software pipeline (16 s-steps/chunk, next chunk's loads in flight
// under current chunk's compute). R10: the recurrence step is forced via
// inline PTX to the minimal 12-cyc chain
//     fma(4) -> setp.gt(4, pred-as-data) -> selp(4)
// with the z-selp and the store off the critical path — preventing ptxas from
// predicating (@P add = 13-cyc pred-as-guard) which R9 evidence suggests.
// ---------------------------------------------------------------------------
__global__ __launch_bounds__(64)
void snn_kernel(const float* __restrict__ cur, float* __restrict__ out) {
    const int tid = blockIdx.x * blockDim.x + threadIdx.x;   // 0..8191
    const int b = tid >> 9;          // /512
    const int h = tid & (HH - 1);

    const float* cp = cur + (long)b * SS * HH + h;
    float* op = out + (long)b * SS * TT * HH + h;

    float c[CH], cn[CH];

    // Prologue: load chunk 0.
    #pragma unroll
    for (int j = 0; j < CH; j++) c[j] = __ldg(cp + j * HH);

    float v = 0.0f;
    for (int k = 0; k < SS / CH; k++) {
        // Issue next chunk's loads before touching this chunk's values.
        const int nbase = (k + 1) * CH;
        if (k + 1 < SS / CH) {
            #pragma unroll
            for (int j = 0; j < CH; j++) cn[j] = __ldg(cp + (nbase + j) * HH);
        }

        float* ok = op + k * CH * TT * HH;
        #pragma unroll
        for (int s = 0; s < CH; s++) {
            const float cs = c[s];
            float* o = ok + s * TT * HH;
            #pragma unroll
            for (int t = 0; t < TT; t++) {
                float z;
                // v = 0.9*v + cs; p = v > 1; z = p?1:0; v = p ? v-1 : v
                asm volatile(
                    "{\n\t"
                    ".reg .pred p;\n\t"
                    ".reg .f32 vm;\n\t"
                    "fma.rn.f32 %0, %0, 0F3F666666, %2;\n\t"
                    "setp.gt.f32 p, %0, 0F3F800000;\n\t"
                    "add.f32 vm, %0, 0FBF800000;\n\t"
                    "selp.f32 %1, 0F3F800000, 0F00000000, p;\n\t"
                    "selp.f32 %0, vm, %0, p;\n\t"
                    "}"
                    : "+f"(v), "=f"(z) : "f"(cs));
                o[t * HH] = z;               // off critical path
            }
        }

        #pragma unroll
        for (int j = 0; j < CH; j++) c[j] = cn[j];
    }
}

extern "C" void kernel_launch(void* const* d_in, const int* in_sizes, int n_in,
                              void* d_out, int out_size) {
    const float* x   = (const float*)d_in[0];   // [B,S,I,H] f32
    const float* enc = (const float*)d_in[1];   // [I,H] f32
    float* out = (float*)d_out;                 // [B, S*T, H] f32

    float* cur;
    cudaGetSymbolAddress((void**)&cur, g_cur);

    dim3 g1(H4 / 32, (BB * SS) / 8);            // (4, 128)
    reduce_kernel<<<g1, 256>>>(x, enc, cur);

    snn_kernel<<<(BB * HH) / 64, 64>>>(cur, out);
}

// round 13
// speedup vs baseline: 1.1387x; 1.0634x over previous
#include <cuda_runtime.h>

// Problem constants (fixed shapes from reference setup_inputs)
#define BB 16
#define SS 64
#define II 128
#define HH 512
#define TT 5
#define H4 (HH / 4)   // 128 float4 lanes across H
#define CH 16         // snn: s-steps per chunk (SS/CH = 4 chunks)

// Scratch: cur[b,s,h] = sum_i x[b,s,i,h] * enc[i,h]   (2 MB)
__device__ float g_cur[BB * SS * HH];

// ---------------------------------------------------------------------------
// Kernel 1: weighted reduction over I.
// R13: encoding slice lives in SMEM (32KB, loaded once per CTA) instead of
// relying on L1 residency — at ~3.5 CTAs/SM the per-CTA 64KB slices were
// oversubscribing the 228KB L1, re-reading enc from L2 and inflating LTS
// traffic. Now L2/DRAM sees only the compulsory ~270MB of x (+2MB cur).
// Grid (8, 64), block 256: blockIdx.x -> 16 h4 columns, blockIdx.y -> 16
// bs-rows. Thread (h4c = tid&15, r = tid>>4) owns one (bs, h4) cell.
// ---------------------------------------------------------------------------
__global__ __launch_bounds__(256)
void reduce_kernel(const float* __restrict__ x,
                   const float* __restrict__ enc,
                   float* __restrict__ cur) {
    __shared__ float4 senc[II][16];            // 128 x 16 float4 = 32KB

    const int h4c = threadIdx.x & 15;
    const int r   = threadIdx.x >> 4;          // 0..15
    const int h4g = blockIdx.x;                // 0..7
    const int h4  = h4g * 16 + h4c;            // 0..127
    const int bs  = blockIdx.y * 16 + r;       // 0..1023

    const float4* __restrict__ x4 = reinterpret_cast<const float4*>(x);
    const float4* __restrict__ e4 = reinterpret_cast<const float4*>(enc);

    // Load the 128(i) x 16(h4) encoding slice into SMEM (each thread 8 rows).
    {
        const int li = threadIdx.x >> 4;       // 0..15
        #pragma unroll
        for (int j = 0; j < 8; j++) {
            const int i = li + j * 16;
            senc[i][h4c] = e4[i * H4 + h4];
        }
    }
    __syncthreads();

    const float4* xp = x4 + (long)bs * II * H4 + h4;

    float4 acc = make_float4(0.f, 0.f, 0.f, 0.f);

    #pragma unroll 8
    for (int i = 0; i < II; i++) {
        float4 xv = __ldcs(xp + i * H4);       // streaming, evict-first
        float4 ev = senc[i][h4c];              // SMEM, conflict-free
        acc.x = fmaf(xv.x, ev.x, acc.x);
        acc.y = fmaf(xv.y, ev.y, acc.y);
        acc.z = fmaf(xv.z, ev.z, acc.z);
        acc.w = fmaf(xv.w, ev.w, acc.w);
    }

    __stcs(reinterpret_cast<float4*>(cur) + (long)bs * H4 + h4, acc);
}

// ---------------------------------------------------------------------------
// Kernel 2: LIF dynamics (R9 form — best measured, 8.93us). One thread per
// (b,h) chain, 8192 chains. Chunked software pipeline: 16 preloaded cur
// values per chunk, next chunk's 16 loads in flight under the 80-step
// recurrence. Per-step chain ~12-13cyc: FFMA -> {FSETP || FADD} -> FSEL,
// z-select + STG off-path.
// ---------------------------------------------------------------------------
__global__ __launch_bounds__(64)
void snn_kernel(const float* __restrict__ cur, float* __restrict__ out) {
    const int tid = blockIdx.x * blockDim.x + threadIdx.x;   // 0..8191
    const int b = tid >> 9;          // /512
    const int h = tid & (HH - 1);

    const float* cp = cur + (long)b * SS * HH + h;
    float* op = out + (long)b * SS * TT * HH + h;

    float c[CH], cn[CH];

    // Prologue: load chunk 0.
    #pragma unroll
    for (int j = 0; j < CH; j++) c[j] = __ldg(cp + j * HH);

    float v = 0.0f;
    for (int k = 0; k < SS / CH; k++) {
        // Issue next chunk's loads before touching this chunk's values.
        const int nbase = (k + 1) * CH;
        if (k + 1 < SS / CH) {
            #pragma unroll
            for (int j = 0; j < CH; j++) cn[j] = __ldg(cp + (nbase + j) * HH);
        }

        float* ok = op + k * CH * TT * HH;
        #pragma unroll
        for (int s = 0; s < CH; s++) {
            const float cs = c[s];
            float* o = ok + s * TT * HH;
            #pragma unroll
            for (int t = 0; t < TT; t++) {
                v = fmaf(0.9f, v, cs);           // v = ALPHA*v + i_t   (4 cyc)
                const bool  p   = (v > 1.0f);    // FSETP, off FFMA     (4 cyc)
                const float vm1 = v - 1.0f;      // FADD, || with FSETP
                o[t * HH] = p ? 1.0f : 0.0f;     // z, off critical path
                v = p ? vm1 : v;                 // FSEL                (4 cyc)
            }
        }

        #pragma unroll
        for (int j = 0; j < CH; j++) c[j] = cn[j];
    }
}

extern "C" void kernel_launch(void* const* d_in, const int* in_sizes, int n_in,
                              void* d_out, int out_size) {
    const float* x   = (const float*)d_in[0];   // [B,S,I,H] f32
    const float* enc = (const float*)d_in[1];   // [I,H] f32
    float* out = (float*)d_out;                 // [B, S*T, H] f32

    float* cur;
    cudaGetSymbolAddress((void**)&cur, g_cur);

    dim3 g1(8, 64);                             // 512 CTAs
    reduce_kernel<<<g1, 256>>>(x, enc, cur);

    snn_kernel<<<(BB * HH) / 64, 64>>>(cur, out);
}